// round 8
// baseline (speedup 1.0000x reference)
#include <cuda_runtime.h>

#define B_DIM 8
#define CIN 512
#define COUT 3
#define WDIM 512
#define HW 65536           // 256*256
#define CONV_CLAMP 256.0f

// Staging for per-(batch, channel) coefficient triples:
//   g_m4[b*CIN+c] = (weight[0][c], weight[1][c], weight[2][c], 0) * styles[b][c]
__device__ float4 g_m4[B_DIM * CIN];

// Per-batch arrival counters (monotonic across graph replays; cohort = 64 CTAs.
// target = (start/64+1)*64, so no reset is needed -> deterministic per run).
__device__ unsigned int g_bar[B_DIM];

// ---------------------------------------------------------------------------
// Fused kernel, barrier-hiding version.
// grid = (64, 8), block = 256. All 512 CTAs co-resident (4/SM x 148 = 592).
//
// Phase 1 : warp w computes style coeffs for channel c = bx*8 + w (own set),
//           writes them to smem AND g_m4.
// Arrive  : tid0 release-fences and atomicAdd's the cohort counter (no wait).
// Overlap : stream the 8 SELF-OWNED c-rows (x-loads need no barrier) —
//           ~2.4us of DRAM work hiding the cohort's phase-1 tail.
// Wait    : tid0 spins (usually already complete), acquire fence.
// Phase 2 : load remaining 504 coeffs, stream c in [0,bx*8) and [bx*8+8,512)
//           with the frozen R3 loop body (unroll 4, __ldcs, m0/m1/m2 smem).
// ---------------------------------------------------------------------------
__global__ void __launch_bounds__(256)
torgb_fused_kernel(const float* __restrict__ x,
                   const float* __restrict__ w,
                   const float* __restrict__ weight,
                   const float* __restrict__ bias,
                   const float* __restrict__ affine_w,
                   const float* __restrict__ affine_b,
                   float* __restrict__ out)
{
    __shared__ float m0[CIN];
    __shared__ float m1[CIN];
    __shared__ float m2[CIN];

    const int b    = blockIdx.y;
    const int bx   = blockIdx.x;
    const int tid  = threadIdx.x;
    const int warp = tid >> 5;
    const int lane = tid & 31;
    const int cOwn = bx * 8;                  // this CTA's owned channel base

    // ---- Phase 1: compute own 8 coefficients (c = cOwn + warp) ----
    {
        const int c = cOwn + warp;
        const float* __restrict__ arow = affine_w + (size_t)c * WDIM;
        const float* __restrict__ wrow = w + (size_t)b * WDIM;
        float sum = 0.0f;
#pragma unroll
        for (int j = 0; j < WDIM / 32; ++j) {
            const int k = lane + 32 * j;
            sum = fmaf(__ldg(&arow[k]), __ldg(&wrow[k]), sum);
        }
#pragma unroll
        for (int off = 16; off > 0; off >>= 1)
            sum += __shfl_xor_sync(0xffffffffu, sum, off);

        if (lane == 0) {
            const float affine_gain = 1.0f / sqrtf((float)WDIM);
            const float cin_gain    = 1.0f / sqrtf((float)CIN);
            const float style = (sum * affine_gain + affine_b[c]) * cin_gain;
            float4 m;
            m.x = weight[0 * CIN + c] * style;
            m.y = weight[1 * CIN + c] * style;
            m.z = weight[2 * CIN + c] * style;
            m.w = 0.0f;
            g_m4[b * CIN + c] = m;
            m0[c] = m.x;                      // own coeffs straight to smem
            m1[c] = m.y;
            m2[c] = m.z;
        }
    }
    __syncthreads();                          // own coeffs visible in smem

    // ---- Early arrive (release): no wait yet ----
    unsigned int target = 0;
    if (tid == 0) {
        __threadfence();                      // publish our g_m4 writes
        const unsigned int start = atomicAdd(&g_bar[b], 1u);
        target = (start / 64u + 1u) * 64u;
    }

    // ---- Overlap: stream the 8 self-owned c-rows while cohort finishes ----
    const int hw4 = bx * blockDim.x + tid;    // index in float4 units
    const float4* __restrict__ x4 =
        (const float4*)(x + (size_t)b * CIN * HW);

    float4 a0 = make_float4(0.f, 0.f, 0.f, 0.f);
    float4 a1 = make_float4(0.f, 0.f, 0.f, 0.f);
    float4 a2 = make_float4(0.f, 0.f, 0.f, 0.f);

#define BODY(c)                                                           \
    {                                                                     \
        const float4 xv = __ldcs(&x4[(size_t)(c) * (HW / 4) + hw4]);      \
        const float c0 = m0[(c)];                                         \
        const float c1 = m1[(c)];                                         \
        const float c2 = m2[(c)];                                         \
        a0.x = fmaf(xv.x, c0, a0.x); a0.y = fmaf(xv.y, c0, a0.y);         \
        a0.z = fmaf(xv.z, c0, a0.z); a0.w = fmaf(xv.w, c0, a0.w);         \
        a1.x = fmaf(xv.x, c1, a1.x); a1.y = fmaf(xv.y, c1, a1.y);         \
        a1.z = fmaf(xv.z, c1, a1.z); a1.w = fmaf(xv.w, c1, a1.w);         \
        a2.x = fmaf(xv.x, c2, a2.x); a2.y = fmaf(xv.y, c2, a2.y);         \
        a2.z = fmaf(xv.z, c2, a2.z); a2.w = fmaf(xv.w, c2, a2.w);         \
    }

#pragma unroll 4
    for (int c = cOwn; c < cOwn + 8; ++c)
        BODY(c)

    // ---- Now wait (usually already satisfied) ----
    if (tid == 0) {
        volatile unsigned int* ctr = &g_bar[b];
        while (*ctr < target)
            __nanosleep(64);
        __threadfence();                      // acquire
    }
    __syncthreads();

    // ---- Load the other 504 coefficients (load all 512; own 8 overwrite
    //      with identical values — cheaper than excluding them) ----
    for (int c = tid; c < CIN; c += blockDim.x) {
        const float4 m = __ldcg(&g_m4[b * CIN + c]);
        m0[c] = m.x;
        m1[c] = m.y;
        m2[c] = m.z;
    }
    __syncthreads();

    // ---- Phase 2: stream the remaining 504 c-rows (two unroll-4 loops,
    //      trip counts are multiples of 8) ----
#pragma unroll 4
    for (int c = 0; c < cOwn; ++c)
        BODY(c)
#pragma unroll 4
    for (int c = cOwn + 8; c < CIN; ++c)
        BODY(c)
#undef BODY

    const float bv0 = bias[0];
    const float bv1 = bias[1];
    const float bv2 = bias[2];

#define CLAMP1(v) fminf(fmaxf((v), -CONV_CLAMP), CONV_CLAMP)
    float4 o0 = make_float4(CLAMP1(a0.x + bv0), CLAMP1(a0.y + bv0),
                            CLAMP1(a0.z + bv0), CLAMP1(a0.w + bv0));
    float4 o1 = make_float4(CLAMP1(a1.x + bv1), CLAMP1(a1.y + bv1),
                            CLAMP1(a1.z + bv1), CLAMP1(a1.w + bv1));
    float4 o2 = make_float4(CLAMP1(a2.x + bv2), CLAMP1(a2.y + bv2),
                            CLAMP1(a2.z + bv2), CLAMP1(a2.w + bv2));
#undef CLAMP1

    float4* __restrict__ out4 = (float4*)out;
    const size_t obase = (size_t)b * COUT * (HW / 4);
    __stcs(&out4[obase + 0 * (HW / 4) + hw4], o0);
    __stcs(&out4[obase + 1 * (HW / 4) + hw4], o1);
    __stcs(&out4[obase + 2 * (HW / 4) + hw4], o2);
}

// ---------------------------------------------------------------------------
// Launch
//   d_in[0] = x        [B, CIN, H, W]  f32
//   d_in[1] = w        [B, WDIM]       f32
//   d_in[2] = weight   [COUT, CIN,1,1] f32
//   d_in[3] = bias     [COUT]          f32
//   d_in[4] = affine_w [CIN, WDIM]     f32
//   d_in[5] = affine_b [CIN]           f32
// ---------------------------------------------------------------------------
extern "C" void kernel_launch(void* const* d_in, const int* in_sizes, int n_in,
                              void* d_out, int out_size)
{
    const float* x        = (const float*)d_in[0];
    const float* w        = (const float*)d_in[1];
    const float* weight   = (const float*)d_in[2];
    const float* bias     = (const float*)d_in[3];
    const float* affine_w = (const float*)d_in[4];
    const float* affine_b = (const float*)d_in[5];
    float* out = (float*)d_out;

    dim3 cgrid(HW / 4 / 256, B_DIM);
    torgb_fused_kernel<<<cgrid, 256>>>(x, w, weight, bias,
                                       affine_w, affine_b, out);
}

// round 9
// speedup vs baseline: 1.1794x; 1.1794x over previous
#include <cuda_runtime.h>

#define B_DIM 8
#define CIN 512
#define COUT 3
#define WDIM 512
#define HW 65536           // 256*256
#define CONV_CLAMP 256.0f

// Staging for per-(batch, channel) coefficient triples:
//   g_m4[b*CIN+c] = (weight[0][c], weight[1][c], weight[2][c], 0) * styles[b][c]
__device__ float4 g_m4[B_DIM * CIN];

// Per-batch arrival counters (monotonic across graph replays; cohort = 64 CTAs.
// target = (start/64+1)*64, so no reset is needed -> deterministic per run).
__device__ unsigned int g_bar[B_DIM];

// ---------------------------------------------------------------------------
// Fused kernel (R7 structure, verified 155.7us) + L2 prefetch in the barrier
// window. grid = (64, 8), block = 256; all 512 CTAs co-resident (592 slots).
//
// Phase 1 : warp w computes style coeff for channel c = bx*8+w, stages g_m4.
// Arrive  : tid0 release-fence + atomicAdd (no wait yet).
// Prefetch: one thread per 128B line issues prefetch.global.L2 for the first
//           PREF_ROWS c-rows of this CTA's stripe — keeps DRAM busy during
//           the otherwise memory-quiet barrier window. No regs, no loop change.
// Wait    : tid0 spins; acquire fence.
// Phase 2 : coeff smem fill + the FROZEN single 0..512 stream loop
//           (unroll 4, __ldcs, m0/m1/m2 smem, __stcs). Do not restructure.
// ---------------------------------------------------------------------------
#define PREF_ROWS 12

__global__ void __launch_bounds__(256)
torgb_fused_kernel(const float* __restrict__ x,
                   const float* __restrict__ w,
                   const float* __restrict__ weight,
                   const float* __restrict__ bias,
                   const float* __restrict__ affine_w,
                   const float* __restrict__ affine_b,
                   float* __restrict__ out)
{
    __shared__ float m0[CIN];
    __shared__ float m1[CIN];
    __shared__ float m2[CIN];

    const int b    = blockIdx.y;
    const int bx   = blockIdx.x;
    const int tid  = threadIdx.x;
    const int warp = tid >> 5;
    const int lane = tid & 31;

    const int hw4 = bx * blockDim.x + tid;    // index in float4 units
    const float4* __restrict__ x4 =
        (const float4*)(x + (size_t)b * CIN * HW);

    // ---- Phase 1: compute this CTA's 8 coefficients (c = bx*8 + warp) ----
    {
        const int c = bx * 8 + warp;
        const float* __restrict__ arow = affine_w + (size_t)c * WDIM;
        const float* __restrict__ wrow = w + (size_t)b * WDIM;
        float sum = 0.0f;
#pragma unroll
        for (int j = 0; j < WDIM / 32; ++j) {
            const int k = lane + 32 * j;
            sum = fmaf(__ldg(&arow[k]), __ldg(&wrow[k]), sum);
        }
#pragma unroll
        for (int off = 16; off > 0; off >>= 1)
            sum += __shfl_xor_sync(0xffffffffu, sum, off);

        if (lane == 0) {
            const float affine_gain = 1.0f / sqrtf((float)WDIM);
            const float cin_gain    = 1.0f / sqrtf((float)CIN);
            const float style = (sum * affine_gain + affine_b[c]) * cin_gain;
            float4 m;
            m.x = weight[0 * CIN + c] * style;
            m.y = weight[1 * CIN + c] * style;
            m.z = weight[2 * CIN + c] * style;
            m.w = 0.0f;
            g_m4[b * CIN + c] = m;
        }
    }
    __syncthreads();                 // all warps done writing g_m4

    // ---- Early arrive (release); wait comes after the prefetch burst ----
    unsigned int target = 0;
    if (tid == 0) {
        __threadfence();             // publish our g_m4 writes
        const unsigned int start = atomicAdd(&g_bar[b], 1u);
        target = (start / 64u + 1u) * 64u;
    }

    // ---- Prefetch the first PREF_ROWS c-rows of this CTA's stripe into L2.
    //      One thread per 128B line (8 float4). Fire-and-forget. ----
    if ((tid & 7) == 0) {
#pragma unroll
        for (int c = 0; c < PREF_ROWS; ++c) {
            const float4* p = &x4[(size_t)c * (HW / 4) + hw4];
            asm volatile("prefetch.global.L2 [%0];" :: "l"(p));
        }
    }

    // ---- Wait for the batch cohort (64 CTAs) ----
    if (tid == 0) {
        volatile unsigned int* ctr = &g_bar[b];
        while (*ctr < target)
            __nanosleep(32);
        __threadfence();             // acquire
    }
    __syncthreads();

    // ---- Coefficient fill for batch b ----
    for (int c = tid; c < CIN; c += blockDim.x) {
        const float4 m = __ldcg(&g_m4[b * CIN + c]);
        m0[c] = m.x;
        m1[c] = m.y;
        m2[c] = m.z;
    }
    __syncthreads();

    // ---- Phase 2: the frozen streaming loop (single fixed 0..512) ----
    float4 a0 = make_float4(0.f, 0.f, 0.f, 0.f);
    float4 a1 = make_float4(0.f, 0.f, 0.f, 0.f);
    float4 a2 = make_float4(0.f, 0.f, 0.f, 0.f);

#pragma unroll 4
    for (int c = 0; c < CIN; ++c) {
        const float4 xv = __ldcs(&x4[(size_t)c * (HW / 4) + hw4]);
        const float c0 = m0[c];
        const float c1 = m1[c];
        const float c2 = m2[c];
        a0.x = fmaf(xv.x, c0, a0.x); a0.y = fmaf(xv.y, c0, a0.y);
        a0.z = fmaf(xv.z, c0, a0.z); a0.w = fmaf(xv.w, c0, a0.w);
        a1.x = fmaf(xv.x, c1, a1.x); a1.y = fmaf(xv.y, c1, a1.y);
        a1.z = fmaf(xv.z, c1, a1.z); a1.w = fmaf(xv.w, c1, a1.w);
        a2.x = fmaf(xv.x, c2, a2.x); a2.y = fmaf(xv.y, c2, a2.y);
        a2.z = fmaf(xv.z, c2, a2.z); a2.w = fmaf(xv.w, c2, a2.w);
    }

    const float bv0 = bias[0];
    const float bv1 = bias[1];
    const float bv2 = bias[2];

#define CLAMP1(v) fminf(fmaxf((v), -CONV_CLAMP), CONV_CLAMP)
    float4 o0 = make_float4(CLAMP1(a0.x + bv0), CLAMP1(a0.y + bv0),
                            CLAMP1(a0.z + bv0), CLAMP1(a0.w + bv0));
    float4 o1 = make_float4(CLAMP1(a1.x + bv1), CLAMP1(a1.y + bv1),
                            CLAMP1(a1.z + bv1), CLAMP1(a1.w + bv1));
    float4 o2 = make_float4(CLAMP1(a2.x + bv2), CLAMP1(a2.y + bv2),
                            CLAMP1(a2.z + bv2), CLAMP1(a2.w + bv2));
#undef CLAMP1

    float4* __restrict__ out4 = (float4*)out;
    const size_t obase = (size_t)b * COUT * (HW / 4);
    __stcs(&out4[obase + 0 * (HW / 4) + hw4], o0);
    __stcs(&out4[obase + 1 * (HW / 4) + hw4], o1);
    __stcs(&out4[obase + 2 * (HW / 4) + hw4], o2);
}

// ---------------------------------------------------------------------------
// Launch
//   d_in[0] = x        [B, CIN, H, W]  f32
//   d_in[1] = w        [B, WDIM]       f32
//   d_in[2] = weight   [COUT, CIN,1,1] f32
//   d_in[3] = bias     [COUT]          f32
//   d_in[4] = affine_w [CIN, WDIM]     f32
//   d_in[5] = affine_b [CIN]           f32
// ---------------------------------------------------------------------------
extern "C" void kernel_launch(void* const* d_in, const int* in_sizes, int n_in,
                              void* d_out, int out_size)
{
    const float* x        = (const float*)d_in[0];
    const float* w        = (const float*)d_in[1];
    const float* weight   = (const float*)d_in[2];
    const float* bias     = (const float*)d_in[3];
    const float* affine_w = (const float*)d_in[4];
    const float* affine_b = (const float*)d_in[5];
    float* out = (float*)d_out;

    dim3 cgrid(HW / 4 / 256, B_DIM);
    torgb_fused_kernel<<<cgrid, 256>>>(x, w, weight, bias,
                                       affine_w, affine_b, out);
}